// round 2
// baseline (speedup 1.0000x reference)
#include <cuda_runtime.h>
#include <cuda_bf16.h>

// ---------------- problem constants ----------------
#define BATCH 32
#define DIM   7168
#define H     128
#define QLR   1536
#define KVLR  512
#define DN    128
#define DR    64
#define DV    128
#define QKD   192          // DN + DR
#define MAXS  4096
#define QDIM  (H*QKD)      // 24576
#define KCAT  (KVLR+DR)    // 576
#define ODIM  (H*DV)       // 16384

#define SCALE_F 0.07216878364870322f   // 192^-0.5
#define EPS_F   1e-6f

typedef unsigned long long ull;

// ---------------- f32x2 helpers ----------------
__device__ __forceinline__ ull fma2(ull a, ull b, ull c) {
    ull d;
    asm("fma.rn.f32x2 %0, %1, %2, %3;" : "=l"(d) : "l"(a), "l"(b), "l"(c));
    return d;
}
__device__ __forceinline__ ull dup2(float x) {
    ull d;
    asm("mov.b64 %0, {%1, %1};" : "=l"(d) : "f"(x));
    return d;
}
__device__ __forceinline__ float2 u2f(ull v) {
    float2 f;
    f.x = __uint_as_float((unsigned)(v & 0xffffffffull));
    f.y = __uint_as_float((unsigned)(v >> 32));
    return f;
}

// ---------------- scratch (device globals; no allocation allowed) ----------------
__device__ __align__(16) float g_qlat  [BATCH * QLR];
__device__ __align__(16) float g_kvfull[BATCH * KCAT];
__device__ __align__(16) float g_kvnew [BATCH * KVLR];
__device__ __align__(16) float g_penew [BATCH * DR];
__device__ __align__(16) float g_q     [BATCH * QDIM];
__device__ __align__(16) float g_qcat  [BATCH * H * KCAT];           // pre-scaled by SCALE
__device__ __align__(16) float g_scores[(long long)BATCH * H * MAXS];
__device__ __align__(16) float g_olat  [BATCH * H * KVLR];
__device__ __align__(16) float g_ohead [BATCH * ODIM];

// ---------------- reductions ----------------
__device__ __forceinline__ float warpSum(float v) {
#pragma unroll
    for (int o = 16; o; o >>= 1) v += __shfl_xor_sync(0xffffffffu, v, o);
    return v;
}
__device__ __forceinline__ float warpMax(float v) {
#pragma unroll
    for (int o = 16; o; o >>= 1) v = fmaxf(v, __shfl_xor_sync(0xffffffffu, v, o));
    return v;
}
__device__ __forceinline__ float blockSum256(float v) {
    __shared__ float sm[8];
    int lane = threadIdx.x & 31, w = threadIdx.x >> 5;
    __syncthreads();
    v = warpSum(v);
    if (!lane) sm[w] = v;
    __syncthreads();
    float r = 0.f;
#pragma unroll
    for (int i = 0; i < 8; i++) r += sm[i];
    return r;
}
__device__ __forceinline__ float blockMax256(float v) {
    __shared__ float sm[8];
    int lane = threadIdx.x & 31, w = threadIdx.x >> 5;
    __syncthreads();
    v = warpMax(v);
    if (!lane) sm[w] = v;
    __syncthreads();
    float r = -1e30f;
#pragma unroll
    for (int i = 0; i < 8; i++) r = fmaxf(r, sm[i]);
    return r;
}

// ---------------- generic tiled GEMM: C[m,n] = sum_k A[m,k] * B[n,k] ----------------
// Tile: 32(M) x 128(N), K chunked by 32. 256 threads, per-thread 4x4 via f32x2.
#define KC 32
#define BM 32
#define BN 128

__global__ void __launch_bounds__(256) gemm_tn(
    const float* __restrict__ A, const float* __restrict__ B, float* __restrict__ C,
    int M, int N, int K, int lda, int ldb, int ldc,
    long long aB, long long bB, long long cB)
{
    A += (long long)blockIdx.z * aB;
    B += (long long)blockIdx.z * bB;
    C += (long long)blockIdx.z * cB;
    int n0 = blockIdx.x * BN;
    int m0 = blockIdx.y * BM;

    __shared__ __align__(16) ull   As2[KC][BM];
    __shared__ __align__(16) float Bs [KC][BN];

    int tid = threadIdx.x;
    int tx = tid & 31, ty = tid >> 5;
    int lm = tid >> 3;
    int lk = (tid & 7) * 4;

    ull acc[8];
#pragma unroll
    for (int i = 0; i < 8; i++) acc[i] = 0ull;

    for (int k0 = 0; k0 < K; k0 += KC) {
        {
            float4 v = *(const float4*)(A + (long long)(m0 + lm) * lda + k0 + lk);
            As2[lk + 0][lm] = dup2(v.x);
            As2[lk + 1][lm] = dup2(v.y);
            As2[lk + 2][lm] = dup2(v.z);
            As2[lk + 3][lm] = dup2(v.w);
        }
#pragma unroll
        for (int i = 0; i < 4; i++) {
            int n = lm + i * 32;
            float4 v = make_float4(0.f, 0.f, 0.f, 0.f);
            if (n0 + n < N)
                v = *(const float4*)(B + (long long)(n0 + n) * ldb + k0 + lk);
            Bs[lk + 0][n] = v.x;
            Bs[lk + 1][n] = v.y;
            Bs[lk + 2][n] = v.z;
            Bs[lk + 3][n] = v.w;
        }
        __syncthreads();
#pragma unroll
        for (int kk = 0; kk < KC; kk++) {
            ulonglong2 a01 = *(const ulonglong2*)&As2[kk][ty * 4 + 0];
            ulonglong2 a23 = *(const ulonglong2*)&As2[kk][ty * 4 + 2];
            ulonglong2 bq  = *(const ulonglong2*)&Bs[kk][tx * 4];
            acc[0] = fma2(a01.x, bq.x, acc[0]); acc[1] = fma2(a01.x, bq.y, acc[1]);
            acc[2] = fma2(a01.y, bq.x, acc[2]); acc[3] = fma2(a01.y, bq.y, acc[3]);
            acc[4] = fma2(a23.x, bq.x, acc[4]); acc[5] = fma2(a23.x, bq.y, acc[5]);
            acc[6] = fma2(a23.y, bq.x, acc[6]); acc[7] = fma2(a23.y, bq.y, acc[7]);
        }
        __syncthreads();
    }

    int nb = n0 + tx * 4;
#pragma unroll
    for (int m = 0; m < 4; m++) {
        float2 lo = u2f(acc[m * 2 + 0]);
        float2 hi = u2f(acc[m * 2 + 1]);
        float* cp = C + (long long)(m0 + ty * 4 + m) * ldc + nb;
        if (nb + 3 < N) {
            cp[0] = lo.x; cp[1] = lo.y; cp[2] = hi.x; cp[3] = hi.y;
        } else {
            if (nb + 0 < N) cp[0] = lo.x;
            if (nb + 1 < N) cp[1] = lo.y;
            if (nb + 2 < N) cp[2] = hi.x;
            if (nb + 3 < N) cp[3] = hi.y;
        }
    }
}

// ---------------- rmsnorm (in place) ----------------
__global__ void __launch_bounds__(256) rmsnorm_kernel(float* __restrict__ v,
                                                      const float* __restrict__ w, int n)
{
    int b = blockIdx.x;
    float* row = v + (long long)b * n;
    float ss = 0.f;
    for (int i = threadIdx.x; i < n; i += 256) { float x = row[i]; ss += x * x; }
    ss = blockSum256(ss);
    __shared__ float s_scale;
    if (threadIdx.x == 0) s_scale = rsqrtf(ss / (float)n + EPS_F);
    __syncthreads();
    float sc = s_scale;
    for (int i = threadIdx.x; i < n; i += 256) row[i] = row[i] * sc * w[i];
}

// ---------------- kv prep: rmsnorm(kv) + rope(k_pe) ----------------
__global__ void __launch_bounds__(256) kvprep_kernel(
    const float* __restrict__ kvfull, const float* __restrict__ w,
    const float* __restrict__ fc, const float* __restrict__ fs,
    float* __restrict__ kvnew, float* __restrict__ penew)
{
    int b = blockIdx.x;
    const float* row = kvfull + (long long)b * KCAT;
    float ss = 0.f;
    for (int i = threadIdx.x; i < KVLR; i += 256) { float x = row[i]; ss += x * x; }
    ss = blockSum256(ss);
    __shared__ float s_scale;
    if (threadIdx.x == 0) s_scale = rsqrtf(ss / (float)KVLR + EPS_F);
    __syncthreads();
    float sc = s_scale;
    for (int i = threadIdx.x; i < KVLR; i += 256)
        kvnew[(long long)b * KVLR + i] = row[i] * sc * w[i];
    if (threadIdx.x < 32) {
        int i = threadIdx.x;
        float x1 = row[KVLR + 2 * i], x2 = row[KVLR + 2 * i + 1];
        float c = fc[i], s = fs[i];
        penew[(long long)b * DR + 2 * i]     = x1 * c - x2 * s;
        penew[(long long)b * DR + 2 * i + 1] = x1 * s + x2 * c;
    }
}

// ---------------- q rope -> qcat tail (scaled) ----------------
__global__ void __launch_bounds__(256) qrope_kernel(
    const float* __restrict__ q, const float* __restrict__ fc,
    const float* __restrict__ fs, float* __restrict__ qcat)
{
    int idx = blockIdx.x * 256 + threadIdx.x;          // over 32*128*32 pairs
    if (idx >= BATCH * H * (DR / 2)) return;
    int i  = idx & 31;
    int bh = idx >> 5;
    int b  = bh >> 7, h = bh & 127;
    const float* src = q + (long long)b * QDIM + h * QKD + DN;
    float x1 = src[2 * i], x2 = src[2 * i + 1];
    float c = fc[i], s = fs[i];
    qcat[(long long)bh * KCAT + KVLR + 2 * i]     = (x1 * c - x2 * s) * SCALE_F;
    qcat[(long long)bh * KCAT + KVLR + 2 * i + 1] = (x1 * s + x2 * c) * SCALE_F;
}

// ---------------- q_abs: qcat[:,:512] = SCALE * q_nope @ wkv_b[:,:128,:] ----------------
__global__ void __launch_bounds__(512) qabs_kernel(
    const float* __restrict__ q, const float* __restrict__ wkvb, float* __restrict__ qcat)
{
    int h = blockIdx.x;
    __shared__ __align__(16) float sq[DN][BATCH];
    int tid = threadIdx.x;
#pragma unroll
    for (int i = 0; i < 8; i++) {
        int idx = tid + i * 512;
        int d = idx >> 5, b = idx & 31;
        sq[d][b] = q[(long long)b * QDIM + h * QKD + d];
    }
    __syncthreads();
    int c = tid;
    ull acc[16];
#pragma unroll
    for (int i = 0; i < 16; i++) acc[i] = 0ull;
    const float* w = wkvb + (long long)h * 256 * KVLR + c;
#pragma unroll 4
    for (int d = 0; d < DN; d++) {
        ull w2 = dup2(w[(long long)d * KVLR]);
#pragma unroll
        for (int bp = 0; bp < 16; bp++) {
            ull qp = *(const ull*)&sq[d][bp * 2];
            acc[bp] = fma2(qp, w2, acc[bp]);
        }
    }
#pragma unroll
    for (int bp = 0; bp < 16; bp++) {
        float2 f = u2f(acc[bp]);
        qcat[((long long)(2 * bp + 0) * H + h) * KCAT + c] = f.x * SCALE_F;
        qcat[((long long)(2 * bp + 1) * H + h) * KCAT + c] = f.y * SCALE_F;
    }
}

// ---------------- scores: S[b,h,t] = qcat[b,h,:] . kvcat[b,t,:] ----------------
__global__ void __launch_bounds__(256) scores_kernel(
    const float* __restrict__ qcat, const float* __restrict__ kvc, const float* __restrict__ pec,
    const float* __restrict__ kvnew, const float* __restrict__ penew,
    float* __restrict__ S, const int* __restrict__ spos_p)
{
    int b    = blockIdx.z;
    int spos = *spos_p;
    const float* A = qcat + (long long)b * H * KCAT;
    float*       C = S    + (long long)b * H * MAXS;
    int t0 = blockIdx.x * BN;
    int h0 = blockIdx.y * BM;

    __shared__ __align__(16) ull   As2[KC][BM];
    __shared__ __align__(16) float Bs [KC][BN];

    int tid = threadIdx.x;
    int tx = tid & 31, ty = tid >> 5;
    int lm = tid >> 3;
    int lk = (tid & 7) * 4;

    ull acc[8];
#pragma unroll
    for (int i = 0; i < 8; i++) acc[i] = 0ull;

    for (int k0 = 0; k0 < KCAT; k0 += KC) {
        {
            float4 v = *(const float4*)(A + (long long)(h0 + lm) * KCAT + k0 + lk);
            As2[lk + 0][lm] = dup2(v.x);
            As2[lk + 1][lm] = dup2(v.y);
            As2[lk + 2][lm] = dup2(v.z);
            As2[lk + 3][lm] = dup2(v.w);
        }
        int kg = k0 + lk;
#pragma unroll
        for (int i = 0; i < 4; i++) {
            int n = lm + i * 32;
            int t = t0 + n;
            const float* src;
            if (kg < KVLR)
                src = (t == spos) ? (kvnew + (long long)b * KVLR + kg)
                                  : (kvc + ((long long)b * MAXS + t) * KVLR + kg);
            else
                src = (t == spos) ? (penew + (long long)b * DR + (kg - KVLR))
                                  : (pec + ((long long)b * MAXS + t) * DR + (kg - KVLR));
            float4 v = *(const float4*)src;
            Bs[lk + 0][n] = v.x;
            Bs[lk + 1][n] = v.y;
            Bs[lk + 2][n] = v.z;
            Bs[lk + 3][n] = v.w;
        }
        __syncthreads();
#pragma unroll
        for (int kk = 0; kk < KC; kk++) {
            ulonglong2 a01 = *(const ulonglong2*)&As2[kk][ty * 4 + 0];
            ulonglong2 a23 = *(const ulonglong2*)&As2[kk][ty * 4 + 2];
            ulonglong2 bq  = *(const ulonglong2*)&Bs[kk][tx * 4];
            acc[0] = fma2(a01.x, bq.x, acc[0]); acc[1] = fma2(a01.x, bq.y, acc[1]);
            acc[2] = fma2(a01.y, bq.x, acc[2]); acc[3] = fma2(a01.y, bq.y, acc[3]);
            acc[4] = fma2(a23.x, bq.x, acc[4]); acc[5] = fma2(a23.x, bq.y, acc[5]);
            acc[6] = fma2(a23.y, bq.x, acc[6]); acc[7] = fma2(a23.y, bq.y, acc[7]);
        }
        __syncthreads();
    }

    int nb = t0 + tx * 4;
#pragma unroll
    for (int m = 0; m < 4; m++) {
        float2 lo = u2f(acc[m * 2 + 0]);
        float2 hi = u2f(acc[m * 2 + 1]);
        float* cp = C + (long long)(h0 + ty * 4 + m) * MAXS + nb;
        cp[0] = lo.x; cp[1] = lo.y; cp[2] = hi.x; cp[3] = hi.y;
    }
}

// ---------------- softmax over t (zero beyond end_pos) ----------------
__global__ void __launch_bounds__(256) softmax_kernel(float* __restrict__ S,
                                                      const int* __restrict__ spos_p)
{
    int row = blockIdx.x;               // b*H + h
    float* p = S + (long long)row * MAXS;
    int end = *spos_p + 1;
    if (end > MAXS) end = MAXS;
    int tid = threadIdx.x;
    float v[16];
    float mx = -1e30f;
#pragma unroll
    for (int j = 0; j < 16; j++) {
        int t = tid + j * 256;
        float x = (t < end) ? p[t] : -1e30f;
        v[j] = x;
        mx = fmaxf(mx, x);
    }
    mx = blockMax256(mx);
    float sum = 0.f;
#pragma unroll
    for (int j = 0; j < 16; j++) {
        int t = tid + j * 256;
        float e = (t < end) ? __expf(v[j] - mx) : 0.f;
        v[j] = e;
        sum += e;
    }
    sum = blockSum256(sum);
    float inv = 1.f / sum;
#pragma unroll
    for (int j = 0; j < 16; j++) {
        int t = tid + j * 256;
        p[t] = v[j] * inv;
    }
}

// ---------------- o_lat: O[b,h,c] = sum_t P[b,h,t] * kvcat[b,t,c] ----------------
__global__ void __launch_bounds__(256) olat_kernel(
    const float* __restrict__ P, const float* __restrict__ kvc,
    const float* __restrict__ kvnew, float* __restrict__ O,
    const int* __restrict__ spos_p)
{
    int b    = blockIdx.z;
    int spos = *spos_p;
    const float* A = P + (long long)b * H * MAXS;   // rows h, cols t
    float*       C = O + (long long)b * H * KVLR;
    int c0 = blockIdx.x * BN;
    int h0 = blockIdx.y * BM;

    __shared__ __align__(16) ull   As2[KC][BM];
    __shared__ __align__(16) float Bs [KC][BN];

    int tid = threadIdx.x;
    int tx = tid & 31, ty = tid >> 5;
    int lm = tid >> 3;
    int lk = (tid & 7) * 4;
    int ln4 = (tid & 31) * 4;
    int lks = tid >> 5;

    ull acc[8];
#pragma unroll
    for (int i = 0; i < 8; i++) acc[i] = 0ull;

    for (int k0 = 0; k0 < MAXS; k0 += KC) {
        {
            float4 v = *(const float4*)(A + (long long)(h0 + lm) * MAXS + k0 + lk);
            As2[lk + 0][lm] = dup2(v.x);
            As2[lk + 1][lm] = dup2(v.y);
            As2[lk + 2][lm] = dup2(v.z);
            As2[lk + 3][lm] = dup2(v.w);
        }
#pragma unroll
        for (int i = 0; i < 4; i++) {
            int kk = lks + i * 8;
            int t = k0 + kk;
            const float* src = (t == spos)
                ? (kvnew + (long long)b * KVLR + c0 + ln4)
                : (kvc + ((long long)b * MAXS + t) * KVLR + c0 + ln4);
            float4 v = *(const float4*)src;
            Bs[kk][ln4 + 0] = v.x;
            Bs[kk][ln4 + 1] = v.y;
            Bs[kk][ln4 + 2] = v.z;
            Bs[kk][ln4 + 3] = v.w;
        }
        __syncthreads();
#pragma unroll
        for (int kk = 0; kk < KC; kk++) {
            ulonglong2 a01 = *(const ulonglong2*)&As2[kk][ty * 4 + 0];
            ulonglong2 a23 = *(const ulonglong2*)&As2[kk][ty * 4 + 2];
            ulonglong2 bq  = *(const ulonglong2*)&Bs[kk][tx * 4];
            acc[0] = fma2(a01.x, bq.x, acc[0]); acc[1] = fma2(a01.x, bq.y, acc[1]);
            acc[2] = fma2(a01.y, bq.x, acc[2]); acc[3] = fma2(a01.y, bq.y, acc[3]);
            acc[4] = fma2(a23.x, bq.x, acc[4]); acc[5] = fma2(a23.x, bq.y, acc[5]);
            acc[6] = fma2(a23.y, bq.x, acc[6]); acc[7] = fma2(a23.y, bq.y, acc[7]);
        }
        __syncthreads();
    }

    int nb = c0 + tx * 4;
#pragma unroll
    for (int m = 0; m < 4; m++) {
        float2 lo = u2f(acc[m * 2 + 0]);
        float2 hi = u2f(acc[m * 2 + 1]);
        float* cp = C + (long long)(h0 + ty * 4 + m) * KVLR + nb;
        cp[0] = lo.x; cp[1] = lo.y; cp[2] = hi.x; cp[3] = hi.y;
    }
}

// ---------------- launch ----------------
extern "C" void kernel_launch(void* const* d_in, const int* in_sizes, int n_in,
                              void* d_out, int out_size)
{
    const float* x        = (const float*)d_in[0];
    const float* fc       = (const float*)d_in[1];
    const float* fs       = (const float*)d_in[2];
    const float* kvc      = (const float*)d_in[3];
    const float* pec      = (const float*)d_in[4];
    const float* wq_a     = (const float*)d_in[5];
    const float* q_norm_w = (const float*)d_in[6];
    const float* wq_b     = (const float*)d_in[7];
    const float* wkv_a    = (const float*)d_in[8];
    const float* kv_norm  = (const float*)d_in[9];
    const float* wkv_b    = (const float*)d_in[10];
    const float* wo       = (const float*)d_in[11];
    const int*   spos     = (const int*)d_in[12];
    float*       out      = (float*)d_out;

    float *qlat, *kvfull, *kvnew, *penew, *q, *qcat, *scores, *olat, *ohead;
    cudaGetSymbolAddress((void**)&qlat,   g_qlat);
    cudaGetSymbolAddress((void**)&kvfull, g_kvfull);
    cudaGetSymbolAddress((void**)&kvnew,  g_kvnew);
    cudaGetSymbolAddress((void**)&penew,  g_penew);
    cudaGetSymbolAddress((void**)&q,      g_q);
    cudaGetSymbolAddress((void**)&qcat,   g_qcat);
    cudaGetSymbolAddress((void**)&scores, g_scores);
    cudaGetSymbolAddress((void**)&olat,   g_olat);
    cudaGetSymbolAddress((void**)&ohead,  g_ohead);

    dim3 blk(256);

    // q_lat = x @ wq_a^T              (32,1536,K=7168)
    gemm_tn<<<dim3(12, 1, 1), blk>>>(x, wq_a, qlat, 32, QLR, DIM, DIM, DIM, QLR, 0, 0, 0);
    // kv_full = x @ wkv_a^T           (32,576,K=7168)
    gemm_tn<<<dim3(5, 1, 1), blk>>>(x, wkv_a, kvfull, 32, KCAT, DIM, DIM, DIM, KCAT, 0, 0, 0);
    // rmsnorm(q_lat)
    rmsnorm_kernel<<<32, 256>>>(qlat, q_norm_w, QLR);
    // kv: rmsnorm + rope(k_pe)
    kvprep_kernel<<<32, 256>>>(kvfull, kv_norm, fc, fs, kvnew, penew);
    // q = q_lat @ wq_b^T              (32,24576,K=1536)
    gemm_tn<<<dim3(192, 1, 1), blk>>>(qlat, wq_b, q, 32, QDIM, QLR, QLR, QLR, QDIM, 0, 0, 0);
    // q_pe rope -> qcat tail
    qrope_kernel<<<512, 256>>>(q, fc, fs, qcat);
    // q_abs -> qcat head
    qabs_kernel<<<128, 512>>>(q, wkv_b, qcat);
    // scores
    scores_kernel<<<dim3(MAXS / BN, H / BM, BATCH), blk>>>(qcat, kvc, pec, kvnew, penew, scores, spos);
    // softmax
    softmax_kernel<<<BATCH * H, 256>>>(scores, spos);
    // o_lat = P @ kvcat
    olat_kernel<<<dim3(KVLR / BN, H / BM, BATCH), blk>>>(scores, kvc, kvnew, olat, spos);
    // o_head[h]: (32,128,K=512) per head, batched over z
    gemm_tn<<<dim3(1, 1, H), blk>>>(olat, wkv_b + 128 * KVLR, ohead,
                                    32, DV, KVLR,
                                    H * KVLR, KVLR, ODIM,
                                    (long long)KVLR, (long long)256 * KVLR, (long long)DV);
    // out = ohead @ wo^T               (32,7168,K=16384)
    gemm_tn<<<dim3(56, 1, 1), blk>>>(ohead, wo, out, 32, DIM, ODIM, ODIM, ODIM, DIM, 0, 0, 0);
}

// round 3
// speedup vs baseline: 1.8429x; 1.8429x over previous
#include <cuda_runtime.h>
#include <cuda_bf16.h>

// ---------------- problem constants ----------------
#define BATCH 32
#define DIM   7168
#define H     128
#define QLR   1536
#define KVLR  512
#define DN    128
#define DR    64
#define DV    128
#define QKD   192          // DN + DR
#define MAXS  4096
#define QDIM  (H*QKD)      // 24576
#define KCAT  (KVLR+DR)    // 576
#define ODIM  (H*DV)       // 16384

#define SCALE_F 0.07216878364870322f   // 192^-0.5
#define EPS_F   1e-6f

typedef unsigned long long ull;

// ---------------- f32x2 helpers ----------------
__device__ __forceinline__ ull fma2(ull a, ull b, ull c) {
    ull d;
    asm("fma.rn.f32x2 %0, %1, %2, %3;" : "=l"(d) : "l"(a), "l"(b), "l"(c));
    return d;
}
__device__ __forceinline__ ull dup2(float x) {
    ull d;
    asm("mov.b64 %0, {%1, %1};" : "=l"(d) : "f"(x));
    return d;
}
__device__ __forceinline__ float2 u2f(ull v) {
    float2 f;
    f.x = __uint_as_float((unsigned)(v & 0xffffffffull));
    f.y = __uint_as_float((unsigned)(v >> 32));
    return f;
}

// ---------------- scratch ----------------
__device__ __align__(16) float g_qlat  [BATCH * QLR];
__device__ __align__(16) float g_kvfull[BATCH * KCAT];
__device__ __align__(16) float g_kvnew [BATCH * KVLR];
__device__ __align__(16) float g_penew [BATCH * DR];
__device__ __align__(16) float g_q     [BATCH * QDIM];
__device__ __align__(16) float g_qcat  [BATCH * H * KCAT];
__device__ __align__(16) float g_scores[(long long)BATCH * H * MAXS];
__device__ __align__(16) float g_olat  [BATCH * H * KVLR];
__device__ __align__(16) float g_ohead [BATCH * ODIM];

// ---------------- reductions ----------------
__device__ __forceinline__ float warpSum(float v) {
#pragma unroll
    for (int o = 16; o; o >>= 1) v += __shfl_xor_sync(0xffffffffu, v, o);
    return v;
}
__device__ __forceinline__ float warpMax(float v) {
#pragma unroll
    for (int o = 16; o; o >>= 1) v = fmaxf(v, __shfl_xor_sync(0xffffffffu, v, o));
    return v;
}
__device__ __forceinline__ float blockSum256(float v) {
    __shared__ float sm[8];
    int lane = threadIdx.x & 31, w = threadIdx.x >> 5;
    __syncthreads();
    v = warpSum(v);
    if (!lane) sm[w] = v;
    __syncthreads();
    float r = 0.f;
#pragma unroll
    for (int i = 0; i < 8; i++) r += sm[i];
    return r;
}
__device__ __forceinline__ float blockMax256(float v) {
    __shared__ float sm[8];
    int lane = threadIdx.x & 31, w = threadIdx.x >> 5;
    __syncthreads();
    v = warpMax(v);
    if (!lane) sm[w] = v;
    __syncthreads();
    float r = -1e30f;
#pragma unroll
    for (int i = 0; i < 8; i++) r = fmaxf(r, sm[i]);
    return r;
}

// =====================================================================
// split-K GEMV: C[32, N] += A[32, K(chunk)] * B[N, K]^T  (atomicAdd)
// Tile 32(M) x BN, KC=16, 256 threads, per-thread 4m x TN.
// Register double-buffered global loads.
// =====================================================================
template<int BN, int TN>
__global__ void __launch_bounds__(256) gemv_splitk(
    const float* __restrict__ A, const float* __restrict__ B, float* __restrict__ C,
    int N, int lda, int ldb, int ldc, int kChunk,
    long long aB, long long bB, long long cB)
{
    A += (long long)blockIdx.z * aB;
    B += (long long)blockIdx.z * bB;
    C += (long long)blockIdx.z * cB;
    const int n0 = blockIdx.x * BN;
    const int ks = blockIdx.y * kChunk;
    const int ke = ks + kChunk;

    __shared__ __align__(16) ull   As2[16][32];
    __shared__ __align__(16) float Bs [16][BN];

    const int tid = threadIdx.x;
    const int tx = tid & 31, ty = tid >> 5;

    const bool aon = tid < 128;
    const int am = tid >> 2, akq = (tid & 3) << 2;
    constexpr int PER = BN / 64;
    const int bn  = tid % BN;
    const int bkq = (tid / BN) * PER;
    const bool bon = (n0 + bn) < N;

    float4 ra = make_float4(0,0,0,0);
    float4 rb[PER];
#pragma unroll
    for (int j = 0; j < PER; j++) rb[j] = make_float4(0,0,0,0);

    // prologue loads
    if (aon) ra = *(const float4*)(A + (long long)am * lda + ks + akq);
    if (bon) {
        const float* bp = B + (long long)(n0 + bn) * ldb + ks + bkq * 4;
#pragma unroll
        for (int j = 0; j < PER; j++) rb[j] = *(const float4*)(bp + j * 4);
    }
    if (aon) {
        As2[akq+0][am] = dup2(ra.x); As2[akq+1][am] = dup2(ra.y);
        As2[akq+2][am] = dup2(ra.z); As2[akq+3][am] = dup2(ra.w);
    }
#pragma unroll
    for (int j = 0; j < PER; j++) {
        Bs[(bkq+j)*4+0][bn] = rb[j].x;
        Bs[(bkq+j)*4+1][bn] = rb[j].y;
        Bs[(bkq+j)*4+2][bn] = rb[j].z;
        Bs[(bkq+j)*4+3][bn] = rb[j].w;
    }
    __syncthreads();

    ull acc[4][TN/2];
#pragma unroll
    for (int m = 0; m < 4; m++)
#pragma unroll
        for (int j = 0; j < TN/2; j++) acc[m][j] = 0ull;

    for (int k0 = ks; k0 < ke; k0 += 16) {
        const bool more = (k0 + 16) < ke;
        if (more) {
            if (aon) ra = *(const float4*)(A + (long long)am * lda + (k0+16) + akq);
            if (bon) {
                const float* bp = B + (long long)(n0 + bn) * ldb + (k0+16) + bkq * 4;
#pragma unroll
                for (int j = 0; j < PER; j++) rb[j] = *(const float4*)(bp + j * 4);
            }
        }
#pragma unroll
        for (int kk = 0; kk < 16; kk++) {
            ulonglong2 a01 = *(const ulonglong2*)&As2[kk][ty*4];
            ulonglong2 a23 = *(const ulonglong2*)&As2[kk][ty*4+2];
            ull a[4] = {a01.x, a01.y, a23.x, a23.y};
            ull bq[TN/2];
            if constexpr (TN == 8) {
                ulonglong2 b0 = *(const ulonglong2*)&Bs[kk][tx*8];
                ulonglong2 b1 = *(const ulonglong2*)&Bs[kk][tx*8+4];
                bq[0]=b0.x; bq[1]=b0.y; bq[2]=b1.x; bq[3]=b1.y;
            } else {
                ulonglong2 b0 = *(const ulonglong2*)&Bs[kk][tx*4];
                bq[0]=b0.x; bq[1]=b0.y;
            }
#pragma unroll
            for (int m = 0; m < 4; m++)
#pragma unroll
                for (int j = 0; j < TN/2; j++)
                    acc[m][j] = fma2(a[m], bq[j], acc[m][j]);
        }
        __syncthreads();
        if (more) {
            if (aon) {
                As2[akq+0][am] = dup2(ra.x); As2[akq+1][am] = dup2(ra.y);
                As2[akq+2][am] = dup2(ra.z); As2[akq+3][am] = dup2(ra.w);
            }
#pragma unroll
            for (int j = 0; j < PER; j++) {
                Bs[(bkq+j)*4+0][bn] = rb[j].x;
                Bs[(bkq+j)*4+1][bn] = rb[j].y;
                Bs[(bkq+j)*4+2][bn] = rb[j].z;
                Bs[(bkq+j)*4+3][bn] = rb[j].w;
            }
        }
        __syncthreads();
    }

    const int nb = n0 + tx * TN;
#pragma unroll
    for (int m = 0; m < 4; m++) {
        float* cp = C + (long long)(ty*4+m) * ldc + nb;
#pragma unroll
        for (int j = 0; j < TN/2; j++) {
            float2 f = u2f(acc[m][j]);
            if (nb + 2*j     < N) atomicAdd(cp + 2*j,     f.x);
            if (nb + 2*j + 1 < N) atomicAdd(cp + 2*j + 1, f.y);
        }
    }
}

// ---------------- rmsnorm (in place) ----------------
__global__ void __launch_bounds__(256) rmsnorm_kernel(float* __restrict__ v,
                                                      const float* __restrict__ w, int n)
{
    int b = blockIdx.x;
    float* row = v + (long long)b * n;
    float ss = 0.f;
    for (int i = threadIdx.x; i < n; i += 256) { float x = row[i]; ss += x * x; }
    ss = blockSum256(ss);
    __shared__ float s_scale;
    if (threadIdx.x == 0) s_scale = rsqrtf(ss / (float)n + EPS_F);
    __syncthreads();
    float sc = s_scale;
    for (int i = threadIdx.x; i < n; i += 256) row[i] = row[i] * sc * w[i];
}

// ---------------- kv prep ----------------
__global__ void __launch_bounds__(256) kvprep_kernel(
    const float* __restrict__ kvfull, const float* __restrict__ w,
    const float* __restrict__ fc, const float* __restrict__ fs,
    float* __restrict__ kvnew, float* __restrict__ penew)
{
    int b = blockIdx.x;
    const float* row = kvfull + (long long)b * KCAT;
    float ss = 0.f;
    for (int i = threadIdx.x; i < KVLR; i += 256) { float x = row[i]; ss += x * x; }
    ss = blockSum256(ss);
    __shared__ float s_scale;
    if (threadIdx.x == 0) s_scale = rsqrtf(ss / (float)KVLR + EPS_F);
    __syncthreads();
    float sc = s_scale;
    for (int i = threadIdx.x; i < KVLR; i += 256)
        kvnew[(long long)b * KVLR + i] = row[i] * sc * w[i];
    if (threadIdx.x < 32) {
        int i = threadIdx.x;
        float x1 = row[KVLR + 2 * i], x2 = row[KVLR + 2 * i + 1];
        float c = fc[i], s = fs[i];
        penew[(long long)b * DR + 2 * i]     = x1 * c - x2 * s;
        penew[(long long)b * DR + 2 * i + 1] = x1 * s + x2 * c;
    }
}

// ---------------- q rope -> qcat tail (scaled) ----------------
__global__ void __launch_bounds__(256) qrope_kernel(
    const float* __restrict__ q, const float* __restrict__ fc,
    const float* __restrict__ fs, float* __restrict__ qcat)
{
    int idx = blockIdx.x * 256 + threadIdx.x;
    if (idx >= BATCH * H * (DR / 2)) return;
    int i  = idx & 31;
    int bh = idx >> 5;
    int b  = bh >> 7, h = bh & 127;
    const float* src = q + (long long)b * QDIM + h * QKD + DN;
    float x1 = src[2 * i], x2 = src[2 * i + 1];
    float c = fc[i], s = fs[i];
    qcat[(long long)bh * KCAT + KVLR + 2 * i]     = (x1 * c - x2 * s) * SCALE_F;
    qcat[(long long)bh * KCAT + KVLR + 2 * i + 1] = (x1 * s + x2 * c) * SCALE_F;
}

// ---------------- q_abs ----------------
__global__ void __launch_bounds__(512) qabs_kernel(
    const float* __restrict__ q, const float* __restrict__ wkvb, float* __restrict__ qcat)
{
    int h = blockIdx.x;
    __shared__ __align__(16) float sq[DN][BATCH];
    int tid = threadIdx.x;
#pragma unroll
    for (int i = 0; i < 8; i++) {
        int idx = tid + i * 512;
        int d = idx >> 5, b = idx & 31;
        sq[d][b] = q[(long long)b * QDIM + h * QKD + d];
    }
    __syncthreads();
    int c = tid;
    ull acc[16];
#pragma unroll
    for (int i = 0; i < 16; i++) acc[i] = 0ull;
    const float* w = wkvb + (long long)h * 256 * KVLR + c;
#pragma unroll 4
    for (int d = 0; d < DN; d++) {
        ull w2 = dup2(w[(long long)d * KVLR]);
#pragma unroll
        for (int bp = 0; bp < 16; bp++) {
            ull qp = *(const ull*)&sq[d][bp * 2];
            acc[bp] = fma2(qp, w2, acc[bp]);
        }
    }
#pragma unroll
    for (int bp = 0; bp < 16; bp++) {
        float2 f = u2f(acc[bp]);
        qcat[((long long)(2 * bp + 0) * H + h) * KCAT + c] = f.x * SCALE_F;
        qcat[((long long)(2 * bp + 1) * H + h) * KCAT + c] = f.y * SCALE_F;
    }
}

// ---------------- KV row loader (16 consecutive k at row t) ----------------
__device__ __forceinline__ void load_kvrow16(float4* rb,
        const float* __restrict__ kvc, const float* __restrict__ pec,
        const float* __restrict__ kvnew, const float* __restrict__ penew,
        int b, int t, int spos, int k0)
{
    const float* src;
    if (k0 < KVLR)
        src = (t == spos) ? (kvnew + (long long)b * KVLR + k0)
                          : (kvc + ((long long)b * MAXS + t) * KVLR + k0);
    else
        src = (t == spos) ? (penew + (long long)b * DR + (k0 - KVLR))
                          : (pec + ((long long)b * MAXS + t) * DR + (k0 - KVLR));
#pragma unroll
    for (int j = 0; j < 4; j++) rb[j] = *(const float4*)(src + j * 4);
}

// =====================================================================
// scores: S[b, h, t] = qcat[b,h,:] . kvcat[b,t,:]   tile 32h x 256t
// =====================================================================
__global__ void __launch_bounds__(256) scores2_kernel(
    const float* __restrict__ qcat, const float* __restrict__ kvc, const float* __restrict__ pec,
    const float* __restrict__ kvnew, const float* __restrict__ penew,
    float* __restrict__ S, const int* __restrict__ spos_p)
{
    const int b = blockIdx.z;
    const int spos = *spos_p;
    const int t0 = blockIdx.x * 256;
    const int h0 = blockIdx.y * 32;
    const float* A = qcat + ((long long)b * H + h0) * KCAT;
    float* C = S + ((long long)b * H + h0) * MAXS;

    __shared__ __align__(16) ull   As2[16][32];
    __shared__ __align__(16) float Bs [16][256];

    const int tid = threadIdx.x, tx = tid & 31, ty = tid >> 5;
    const bool aon = tid < 128;
    const int am = tid >> 2, akq = (tid & 3) << 2;
    const int t = t0 + tid;

    float4 ra = make_float4(0,0,0,0);
    float4 rb[4];

    if (aon) ra = *(const float4*)(A + (long long)am * KCAT + akq);
    load_kvrow16(rb, kvc, pec, kvnew, penew, b, t, spos, 0);
    if (aon) {
        As2[akq+0][am] = dup2(ra.x); As2[akq+1][am] = dup2(ra.y);
        As2[akq+2][am] = dup2(ra.z); As2[akq+3][am] = dup2(ra.w);
    }
#pragma unroll
    for (int j = 0; j < 4; j++) {
        Bs[j*4+0][tid] = rb[j].x; Bs[j*4+1][tid] = rb[j].y;
        Bs[j*4+2][tid] = rb[j].z; Bs[j*4+3][tid] = rb[j].w;
    }
    __syncthreads();

    ull acc[4][4];
#pragma unroll
    for (int m = 0; m < 4; m++)
#pragma unroll
        for (int j = 0; j < 4; j++) acc[m][j] = 0ull;

    for (int k0 = 0; k0 < KCAT; k0 += 16) {
        const bool more = (k0 + 16) < KCAT;
        if (more) {
            if (aon) ra = *(const float4*)(A + (long long)am * KCAT + (k0+16) + akq);
            load_kvrow16(rb, kvc, pec, kvnew, penew, b, t, spos, k0 + 16);
        }
#pragma unroll
        for (int kk = 0; kk < 16; kk++) {
            ulonglong2 a01 = *(const ulonglong2*)&As2[kk][ty*4];
            ulonglong2 a23 = *(const ulonglong2*)&As2[kk][ty*4+2];
            ull a[4] = {a01.x, a01.y, a23.x, a23.y};
            ulonglong2 b0 = *(const ulonglong2*)&Bs[kk][tx*8];
            ulonglong2 b1 = *(const ulonglong2*)&Bs[kk][tx*8+4];
            ull bq[4] = {b0.x, b0.y, b1.x, b1.y};
#pragma unroll
            for (int m = 0; m < 4; m++)
#pragma unroll
                for (int j = 0; j < 4; j++)
                    acc[m][j] = fma2(a[m], bq[j], acc[m][j]);
        }
        __syncthreads();
        if (more) {
            if (aon) {
                As2[akq+0][am] = dup2(ra.x); As2[akq+1][am] = dup2(ra.y);
                As2[akq+2][am] = dup2(ra.z); As2[akq+3][am] = dup2(ra.w);
            }
#pragma unroll
            for (int j = 0; j < 4; j++) {
                Bs[j*4+0][tid] = rb[j].x; Bs[j*4+1][tid] = rb[j].y;
                Bs[j*4+2][tid] = rb[j].z; Bs[j*4+3][tid] = rb[j].w;
            }
        }
        __syncthreads();
    }

    const int nb = t0 + tx * 8;
#pragma unroll
    for (int m = 0; m < 4; m++) {
        float2 f0 = u2f(acc[m][0]), f1 = u2f(acc[m][1]);
        float2 f2 = u2f(acc[m][2]), f3 = u2f(acc[m][3]);
        float* cp = C + (long long)(ty*4+m) * MAXS + nb;
        *(float4*)cp       = make_float4(f0.x, f0.y, f1.x, f1.y);
        *(float4*)(cp + 4) = make_float4(f2.x, f2.y, f3.x, f3.y);
    }
}

// ---------------- softmax ----------------
__global__ void __launch_bounds__(256) softmax_kernel(float* __restrict__ S,
                                                      const int* __restrict__ spos_p)
{
    int row = blockIdx.x;
    float* p = S + (long long)row * MAXS;
    int end = *spos_p + 1;
    if (end > MAXS) end = MAXS;
    int tid = threadIdx.x;
    float v[16];
    float mx = -1e30f;
#pragma unroll
    for (int j = 0; j < 16; j++) {
        int t = tid + j * 256;
        float x = (t < end) ? p[t] : -1e30f;
        v[j] = x;
        mx = fmaxf(mx, x);
    }
    mx = blockMax256(mx);
    float sum = 0.f;
#pragma unroll
    for (int j = 0; j < 16; j++) {
        int t = tid + j * 256;
        float e = (t < end) ? __expf(v[j] - mx) : 0.f;
        v[j] = e;
        sum += e;
    }
    sum = blockSum256(sum);
    float inv = 1.f / sum;
#pragma unroll
    for (int j = 0; j < 16; j++) {
        int t = tid + j * 256;
        p[t] = v[j] * inv;
    }
}

// =====================================================================
// olat: O[b,h,c] = sum_t P[b,h,t] * kvcat[b,t,c]   tile 32h x 128c
// =====================================================================
__global__ void __launch_bounds__(256) olat2_kernel(
    const float* __restrict__ P, const float* __restrict__ kvc,
    const float* __restrict__ kvnew, float* __restrict__ O,
    const int* __restrict__ spos_p)
{
    const int b = blockIdx.z;
    const int spos = *spos_p;
    const int c0 = blockIdx.x * 128;
    const int h0 = blockIdx.y * 32;
    const float* A = P + ((long long)b * H + h0) * MAXS;
    float* C = O + ((long long)b * H + h0) * KVLR;

    __shared__ __align__(16) ull   As2[16][32];
    __shared__ __align__(16) float Bs [16][128];

    const int tid = threadIdx.x, tx = tid & 31, ty = tid >> 5;
    const bool aon = tid < 128;
    const int am = tid >> 2, akq = (tid & 3) << 2;
    const int kkr = tid >> 5;          // 0..7
    const int c4  = (tid & 31) * 4;

    float4 ra = make_float4(0,0,0,0);
    float4 rb[2];

    if (aon) ra = *(const float4*)(A + (long long)am * MAXS + akq);
#pragma unroll
    for (int j = 0; j < 2; j++) {
        int t = kkr + 8*j;
        const float* src = (t == spos) ? (kvnew + (long long)b * KVLR + c0 + c4)
                                       : (kvc + ((long long)b * MAXS + t) * KVLR + c0 + c4);
        rb[j] = *(const float4*)src;
    }
    if (aon) {
        As2[akq+0][am] = dup2(ra.x); As2[akq+1][am] = dup2(ra.y);
        As2[akq+2][am] = dup2(ra.z); As2[akq+3][am] = dup2(ra.w);
    }
#pragma unroll
    for (int j = 0; j < 2; j++)
        *(float4*)&Bs[kkr + 8*j][c4] = rb[j];
    __syncthreads();

    ull acc[4][2];
#pragma unroll
    for (int m = 0; m < 4; m++) { acc[m][0] = 0ull; acc[m][1] = 0ull; }

    for (int k0 = 0; k0 < MAXS; k0 += 16) {
        const bool more = (k0 + 16) < MAXS;
        if (more) {
            if (aon) ra = *(const float4*)(A + (long long)am * MAXS + (k0+16) + akq);
#pragma unroll
            for (int j = 0; j < 2; j++) {
                int t = k0 + 16 + kkr + 8*j;
                const float* src = (t == spos) ? (kvnew + (long long)b * KVLR + c0 + c4)
                                               : (kvc + ((long long)b * MAXS + t) * KVLR + c0 + c4);
                rb[j] = *(const float4*)src;
            }
        }
#pragma unroll
        for (int kk = 0; kk < 16; kk++) {
            ulonglong2 a01 = *(const ulonglong2*)&As2[kk][ty*4];
            ulonglong2 a23 = *(const ulonglong2*)&As2[kk][ty*4+2];
            ull a[4] = {a01.x, a01.y, a23.x, a23.y};
            ulonglong2 b0 = *(const ulonglong2*)&Bs[kk][tx*4];
            ull bq[2] = {b0.x, b0.y};
#pragma unroll
            for (int m = 0; m < 4; m++) {
                acc[m][0] = fma2(a[m], bq[0], acc[m][0]);
                acc[m][1] = fma2(a[m], bq[1], acc[m][1]);
            }
        }
        __syncthreads();
        if (more) {
            if (aon) {
                As2[akq+0][am] = dup2(ra.x); As2[akq+1][am] = dup2(ra.y);
                As2[akq+2][am] = dup2(ra.z); As2[akq+3][am] = dup2(ra.w);
            }
#pragma unroll
            for (int j = 0; j < 2; j++)
                *(float4*)&Bs[kkr + 8*j][c4] = rb[j];
        }
        __syncthreads();
    }

    const int nb = c0 + tx * 4;
#pragma unroll
    for (int m = 0; m < 4; m++) {
        float2 f0 = u2f(acc[m][0]), f1 = u2f(acc[m][1]);
        *(float4*)(C + (long long)(ty*4+m) * KVLR + nb) = make_float4(f0.x, f0.y, f1.x, f1.y);
    }
}

// ---------------- launch ----------------
extern "C" void kernel_launch(void* const* d_in, const int* in_sizes, int n_in,
                              void* d_out, int out_size)
{
    const float* x        = (const float*)d_in[0];
    const float* fc       = (const float*)d_in[1];
    const float* fs       = (const float*)d_in[2];
    const float* kvc      = (const float*)d_in[3];
    const float* pec      = (const float*)d_in[4];
    const float* wq_a     = (const float*)d_in[5];
    const float* q_norm_w = (const float*)d_in[6];
    const float* wq_b     = (const float*)d_in[7];
    const float* wkv_a    = (const float*)d_in[8];
    const float* kv_norm  = (const float*)d_in[9];
    const float* wkv_b    = (const float*)d_in[10];
    const float* wo       = (const float*)d_in[11];
    const int*   spos     = (const int*)d_in[12];
    float*       out      = (float*)d_out;

    float *qlat, *kvfull, *kvnew, *penew, *q, *qcat, *scores, *olat, *ohead;
    cudaGetSymbolAddress((void**)&qlat,   g_qlat);
    cudaGetSymbolAddress((void**)&kvfull, g_kvfull);
    cudaGetSymbolAddress((void**)&kvnew,  g_kvnew);
    cudaGetSymbolAddress((void**)&penew,  g_penew);
    cudaGetSymbolAddress((void**)&q,      g_q);
    cudaGetSymbolAddress((void**)&qcat,   g_qcat);
    cudaGetSymbolAddress((void**)&scores, g_scores);
    cudaGetSymbolAddress((void**)&olat,   g_olat);
    cudaGetSymbolAddress((void**)&ohead,  g_ohead);

    // zero accumulation targets (memset nodes are graph-capturable)
    cudaMemsetAsync(qlat,   0, (size_t)BATCH * QLR  * 4);
    cudaMemsetAsync(kvfull, 0, (size_t)BATCH * KCAT * 4);
    cudaMemsetAsync(q,      0, (size_t)BATCH * QDIM * 4);
    cudaMemsetAsync(ohead,  0, (size_t)BATCH * ODIM * 4);
    cudaMemsetAsync(out,    0, (size_t)out_size * 4);

    dim3 blk(256);

    // q_lat = x @ wq_a^T   (N=1536, K=7168)  6 tiles x 16 splits
    gemv_splitk<256,8><<<dim3(6,16,1), blk>>>(x, wq_a, qlat, QLR, DIM, DIM, QLR, 448, 0,0,0);
    // kv_full = x @ wkv_a^T (N=576, K=7168)  3 tiles x 32 splits
    gemv_splitk<256,8><<<dim3(3,32,1), blk>>>(x, wkv_a, kvfull, KCAT, DIM, DIM, KCAT, 224, 0,0,0);
    // rmsnorm(q_lat)
    rmsnorm_kernel<<<32, 256>>>(qlat, q_norm_w, QLR);
    // kv prep
    kvprep_kernel<<<32, 256>>>(kvfull, kv_norm, fc, fs, kvnew, penew);
    // q = q_lat @ wq_b^T   (N=24576, K=1536) 96 tiles x 3 splits
    gemv_splitk<256,8><<<dim3(96,3,1), blk>>>(qlat, wq_b, q, QDIM, QLR, QLR, QDIM, 512, 0,0,0);
    // q rope tail
    qrope_kernel<<<512, 256>>>(q, fc, fs, qcat);
    // q_abs head
    qabs_kernel<<<128, 512>>>(q, wkv_b, qcat);
    // scores
    scores2_kernel<<<dim3(MAXS/256, H/32, BATCH), blk>>>(qcat, kvc, pec, kvnew, penew, scores, spos);
    // softmax
    softmax_kernel<<<BATCH * H, 256>>>(scores, spos);
    // o_lat
    olat2_kernel<<<dim3(KVLR/128, H/32, BATCH), blk>>>(scores, kvc, kvnew, olat, spos);
    // o_head per head z: A=olat(+z*512, lda 65536), B=wkv_b value part, C=ohead(+z*128)
    gemv_splitk<128,4><<<dim3(1,1,H), blk>>>(olat, wkv_b + 128*KVLR, ohead,
                                             DV, H*KVLR, KVLR, ODIM, KVLR,
                                             (long long)KVLR, (long long)256*KVLR, (long long)DV);
    // out = ohead @ wo^T   (N=7168, K=16384) 28 tiles x 8 splits
    gemv_splitk<256,8><<<dim3(28,8,1), blk>>>(ohead, wo, out, DIM, ODIM, ODIM, DIM, 2048, 0,0,0);
}

// round 4
// speedup vs baseline: 4.8377x; 2.6250x over previous
#include <cuda_runtime.h>
#include <cuda_bf16.h>

// ---------------- problem constants ----------------
#define BATCH 32
#define DIM   7168
#define H     128
#define QLR   1536
#define KVLR  512
#define DN    128
#define DR    64
#define DV    128
#define QKD   192
#define MAXS  4096
#define QDIM  (H*QKD)      // 24576
#define KCAT  (KVLR+DR)    // 576
#define ODIM  (H*DV)       // 16384

#define SCALE_F 0.07216878364870322f
#define EPS_F   1e-6f

typedef unsigned long long ull;

// ---------------- helpers ----------------
__device__ __forceinline__ ull fma2(ull a, ull b, ull c) {
    ull d;
    asm("fma.rn.f32x2 %0, %1, %2, %3;" : "=l"(d) : "l"(a), "l"(b), "l"(c));
    return d;
}
__device__ __forceinline__ ull dup2(float x) {
    ull d;
    asm("mov.b64 %0, {%1, %1};" : "=l"(d) : "f"(x));
    return d;
}
__device__ __forceinline__ float2 u2f(ull v) {
    float2 f;
    f.x = __uint_as_float((unsigned)(v & 0xffffffffull));
    f.y = __uint_as_float((unsigned)(v >> 32));
    return f;
}
__device__ __forceinline__ unsigned f2tf(float f) {
    unsigned u; asm("cvt.rna.tf32.f32 %0, %1;" : "=r"(u) : "f"(f)); return u;
}
// D = A(16x8,row) * B(8x8,col) + D   tf32 inputs, f32 accum
__device__ __forceinline__ void mma8(float* c, const unsigned* a, const unsigned* b) {
    asm volatile("mma.sync.aligned.m16n8k8.row.col.f32.tf32.tf32.f32 "
                 "{%0,%1,%2,%3}, {%4,%5,%6,%7}, {%8,%9}, {%0,%1,%2,%3};"
                 : "+f"(c[0]), "+f"(c[1]), "+f"(c[2]), "+f"(c[3])
                 : "r"(a[0]), "r"(a[1]), "r"(a[2]), "r"(a[3]),
                   "r"(b[0]), "r"(b[1]));
}

// ---------------- scratch ----------------
__device__ __align__(16) float g_qlat  [BATCH * QLR];
__device__ __align__(16) float g_kvfull[BATCH * KCAT];
__device__ __align__(16) float g_kvnew [BATCH * KVLR];
__device__ __align__(16) float g_penew [BATCH * DR];
__device__ __align__(16) float g_q     [BATCH * QDIM];
__device__ __align__(16) float g_qcat  [BATCH * H * KCAT];
__device__ __align__(16) float g_scores[(long long)BATCH * H * MAXS];
__device__ __align__(16) float g_olat  [BATCH * H * KVLR];
__device__ __align__(16) float g_ohead [BATCH * ODIM];

// ---------------- reductions ----------------
__device__ __forceinline__ float warpSum(float v) {
#pragma unroll
    for (int o = 16; o; o >>= 1) v += __shfl_xor_sync(0xffffffffu, v, o);
    return v;
}
__device__ __forceinline__ float warpMax(float v) {
#pragma unroll
    for (int o = 16; o; o >>= 1) v = fmaxf(v, __shfl_xor_sync(0xffffffffu, v, o));
    return v;
}
__device__ __forceinline__ float blockSum256(float v) {
    __shared__ float sm[8];
    int lane = threadIdx.x & 31, w = threadIdx.x >> 5;
    __syncthreads();
    v = warpSum(v);
    if (!lane) sm[w] = v;
    __syncthreads();
    float r = 0.f;
#pragma unroll
    for (int i = 0; i < 8; i++) r += sm[i];
    return r;
}
__device__ __forceinline__ float blockMax256(float v) {
    __shared__ float sm[8];
    int lane = threadIdx.x & 31, w = threadIdx.x >> 5;
    __syncthreads();
    v = warpMax(v);
    if (!lane) sm[w] = v;
    __syncthreads();
    float r = -1e30f;
#pragma unroll
    for (int i = 0; i < 8; i++) r = fmaxf(r, sm[i]);
    return r;
}

// =====================================================================
// TF32 MMA split-K GEMV: C[32, N] += A[32,K(chunk)] * B[N,K]^T (atomic)
// block tile 32m x 256n, KC=16, 8 warps each 32m x 32n
// =====================================================================
__global__ void __launch_bounds__(256) gemv_mma(
    const float* __restrict__ A, const float* __restrict__ B, float* __restrict__ C,
    int lda, int ldb, int ldc, int kChunk)
{
    const int n0 = blockIdx.x * 256;
    const int ks = blockIdx.y * kChunk;
    const int ke = ks + kChunk;

    __shared__ unsigned As[16][40];
    __shared__ unsigned Bs[16][264];

    const int tid = threadIdx.x, lane = tid & 31, wid = tid >> 5;
    const int gid = lane >> 2, tig = lane & 3;
    const int wn = wid * 32;

    const bool aon = tid < 128;
    const int am = tid >> 2, akq = (tid & 3) * 4;
    const int aq = (akq >> 2) & 3;
    const long long brow = (long long)(n0 + tid) * ldb;

    float4 ra = make_float4(0,0,0,0);
    float4 rb[4];

    if (aon) ra = *(const float4*)(A + (long long)am * lda + ks + akq);
#pragma unroll
    for (int j = 0; j < 4; j++) rb[j] = *(const float4*)(B + brow + ks + j*4);

    if (aon) {
        int col = am ^ (8*aq);
        As[akq+0][col] = f2tf(ra.x); As[akq+1][col] = f2tf(ra.y);
        As[akq+2][col] = f2tf(ra.z); As[akq+3][col] = f2tf(ra.w);
    }
#pragma unroll
    for (int j = 0; j < 4; j++) {
        Bs[j*4+0][tid] = f2tf(rb[j].x); Bs[j*4+1][tid] = f2tf(rb[j].y);
        Bs[j*4+2][tid] = f2tf(rb[j].z); Bs[j*4+3][tid] = f2tf(rb[j].w);
    }
    __syncthreads();

    float acc[2][4][4];
#pragma unroll
    for (int mi = 0; mi < 2; mi++)
#pragma unroll
        for (int nj = 0; nj < 4; nj++)
#pragma unroll
            for (int r = 0; r < 4; r++) acc[mi][nj][r] = 0.f;

    for (int k0 = ks; k0 < ke; k0 += 16) {
        const bool more = (k0 + 16) < ke;
        if (more) {
            if (aon) ra = *(const float4*)(A + (long long)am * lda + (k0+16) + akq);
#pragma unroll
            for (int j = 0; j < 4; j++) rb[j] = *(const float4*)(B + brow + (k0+16) + j*4);
        }
#pragma unroll
        for (int s = 0; s < 2; s++) {
            const int kk = s * 8;
            const int key0 = 8 * ((kk >> 2) & 3);
            const int key1 = 8 * (((kk >> 2) + 1) & 3);
            unsigned af[2][4];
#pragma unroll
            for (int mi = 0; mi < 2; mi++) {
                int r0 = mi*16 + gid;
                af[mi][0] = As[kk+tig  ][ r0    ^ key0];
                af[mi][1] = As[kk+tig  ][(r0+8) ^ key0];
                af[mi][2] = As[kk+tig+4][ r0    ^ key1];
                af[mi][3] = As[kk+tig+4][(r0+8) ^ key1];
            }
            unsigned bf[4][2];
#pragma unroll
            for (int nj = 0; nj < 4; nj++) {
                bf[nj][0] = Bs[kk+tig  ][wn + nj*8 + gid];
                bf[nj][1] = Bs[kk+tig+4][wn + nj*8 + gid];
            }
#pragma unroll
            for (int mi = 0; mi < 2; mi++)
#pragma unroll
                for (int nj = 0; nj < 4; nj++)
                    mma8(acc[mi][nj], af[mi], bf[nj]);
        }
        __syncthreads();
        if (more) {
            if (aon) {
                int col = am ^ (8*aq);
                As[akq+0][col] = f2tf(ra.x); As[akq+1][col] = f2tf(ra.y);
                As[akq+2][col] = f2tf(ra.z); As[akq+3][col] = f2tf(ra.w);
            }
#pragma unroll
            for (int j = 0; j < 4; j++) {
                Bs[j*4+0][tid] = f2tf(rb[j].x); Bs[j*4+1][tid] = f2tf(rb[j].y);
                Bs[j*4+2][tid] = f2tf(rb[j].z); Bs[j*4+3][tid] = f2tf(rb[j].w);
            }
        }
        __syncthreads();
    }

#pragma unroll
    for (int mi = 0; mi < 2; mi++)
#pragma unroll
        for (int nj = 0; nj < 4; nj++) {
            float* cp = C + (long long)(mi*16+gid)*ldc + n0 + wn + nj*8 + 2*tig;
            atomicAdd(cp,           acc[mi][nj][0]);
            atomicAdd(cp + 1,       acc[mi][nj][1]);
            atomicAdd(cp + 8*ldc,   acc[mi][nj][2]);
            atomicAdd(cp + 8*ldc+1, acc[mi][nj][3]);
        }
}

// ---------------- rmsnorm (in place) ----------------
__global__ void __launch_bounds__(256) rmsnorm_kernel(float* __restrict__ v,
                                                      const float* __restrict__ w, int n)
{
    int b = blockIdx.x;
    float* row = v + (long long)b * n;
    float ss = 0.f;
    for (int i = threadIdx.x; i < n; i += 256) { float x = row[i]; ss += x * x; }
    ss = blockSum256(ss);
    __shared__ float s_scale;
    if (threadIdx.x == 0) s_scale = rsqrtf(ss / (float)n + EPS_F);
    __syncthreads();
    float sc = s_scale;
    for (int i = threadIdx.x; i < n; i += 256) row[i] = row[i] * sc * w[i];
}

// ---------------- kv prep ----------------
__global__ void __launch_bounds__(256) kvprep_kernel(
    const float* __restrict__ kvfull, const float* __restrict__ w,
    const float* __restrict__ fc, const float* __restrict__ fs,
    float* __restrict__ kvnew, float* __restrict__ penew)
{
    int b = blockIdx.x;
    const float* row = kvfull + (long long)b * KCAT;
    float ss = 0.f;
    for (int i = threadIdx.x; i < KVLR; i += 256) { float x = row[i]; ss += x * x; }
    ss = blockSum256(ss);
    __shared__ float s_scale;
    if (threadIdx.x == 0) s_scale = rsqrtf(ss / (float)KVLR + EPS_F);
    __syncthreads();
    float sc = s_scale;
    for (int i = threadIdx.x; i < KVLR; i += 256)
        kvnew[(long long)b * KVLR + i] = row[i] * sc * w[i];
    if (threadIdx.x < 32) {
        int i = threadIdx.x;
        float x1 = row[KVLR + 2 * i], x2 = row[KVLR + 2 * i + 1];
        float c = fc[i], s = fs[i];
        penew[(long long)b * DR + 2 * i]     = x1 * c - x2 * s;
        penew[(long long)b * DR + 2 * i + 1] = x1 * s + x2 * c;
    }
}

// ---------------- q rope -> qcat tail (scaled) ----------------
__global__ void __launch_bounds__(256) qrope_kernel(
    const float* __restrict__ q, const float* __restrict__ fc,
    const float* __restrict__ fs, float* __restrict__ qcat)
{
    int idx = blockIdx.x * 256 + threadIdx.x;
    if (idx >= BATCH * H * (DR / 2)) return;
    int i  = idx & 31;
    int bh = idx >> 5;
    int b  = bh >> 7, h = bh & 127;
    const float* src = q + (long long)b * QDIM + h * QKD + DN;
    float x1 = src[2 * i], x2 = src[2 * i + 1];
    float c = fc[i], s = fs[i];
    qcat[(long long)bh * KCAT + KVLR + 2 * i]     = (x1 * c - x2 * s) * SCALE_F;
    qcat[(long long)bh * KCAT + KVLR + 2 * i + 1] = (x1 * s + x2 * c) * SCALE_F;
}

// ---------------- q_abs (FFMA, small) ----------------
__global__ void __launch_bounds__(512) qabs_kernel(
    const float* __restrict__ q, const float* __restrict__ wkvb, float* __restrict__ qcat)
{
    int h = blockIdx.x;
    __shared__ __align__(16) float sq[DN][BATCH];
    int tid = threadIdx.x;
#pragma unroll
    for (int i = 0; i < 8; i++) {
        int idx = tid + i * 512;
        int d = idx >> 5, b = idx & 31;
        sq[d][b] = q[(long long)b * QDIM + h * QKD + d];
    }
    __syncthreads();
    int c = tid;
    ull acc[16];
#pragma unroll
    for (int i = 0; i < 16; i++) acc[i] = 0ull;
    const float* w = wkvb + (long long)h * 256 * KVLR + c;
#pragma unroll 4
    for (int d = 0; d < DN; d++) {
        ull w2 = dup2(w[(long long)d * KVLR]);
#pragma unroll
        for (int bp = 0; bp < 16; bp++) {
            ull qp = *(const ull*)&sq[d][bp * 2];
            acc[bp] = fma2(qp, w2, acc[bp]);
        }
    }
#pragma unroll
    for (int bp = 0; bp < 16; bp++) {
        float2 f = u2f(acc[bp]);
        qcat[((long long)(2 * bp + 0) * H + h) * KCAT + c] = f.x * SCALE_F;
        qcat[((long long)(2 * bp + 1) * H + h) * KCAT + c] = f.y * SCALE_F;
    }
}

// ---------------- KV row loader ----------------
__device__ __forceinline__ void load_kvrow16(float4* rb,
        const float* __restrict__ kvc, const float* __restrict__ pec,
        const float* __restrict__ kvnew, const float* __restrict__ penew,
        int b, int t, int spos, int k0)
{
    const float* src;
    if (k0 < KVLR)
        src = (t == spos) ? (kvnew + (long long)b * KVLR + k0)
                          : (kvc + ((long long)b * MAXS + t) * KVLR + k0);
    else
        src = (t == spos) ? (penew + (long long)b * DR + (k0 - KVLR))
                          : (pec + ((long long)b * MAXS + t) * DR + (k0 - KVLR));
#pragma unroll
    for (int j = 0; j < 4; j++) rb[j] = *(const float4*)(src + j * 4);
}

// =====================================================================
// scores (TF32 MMA): tile 64h x 256t, warps 2x4 (32h x 64t each)
// =====================================================================
__global__ void __launch_bounds__(256) scores_mma(
    const float* __restrict__ qcat, const float* __restrict__ kvc, const float* __restrict__ pec,
    const float* __restrict__ kvnew, const float* __restrict__ penew,
    float* __restrict__ S, const int* __restrict__ spos_p)
{
    const int b = blockIdx.z, spos = *spos_p;
    const int t0 = blockIdx.x * 256, h0 = blockIdx.y * 64;
    const float* A = qcat + ((long long)b * H + h0) * KCAT;
    float* C = S + ((long long)b * H + h0) * MAXS;

    __shared__ unsigned As[16][72];
    __shared__ unsigned Bs[16][264];

    const int tid = threadIdx.x, lane = tid & 31, wid = tid >> 5;
    const int gid = lane >> 2, tig = lane & 3;
    const int wh = (wid & 1) * 32, wt = (wid >> 1) * 64;

    const int ah = tid >> 2, akq = (tid & 3) * 4;
    const int acol = ah ^ (8 * ((akq >> 2) & 3));
    const int bt = t0 + tid;

    float4 ra; float4 rb[4];
    ra = *(const float4*)(A + (long long)ah * KCAT + akq);
    load_kvrow16(rb, kvc, pec, kvnew, penew, b, bt, spos, 0);
    As[akq+0][acol] = f2tf(ra.x); As[akq+1][acol] = f2tf(ra.y);
    As[akq+2][acol] = f2tf(ra.z); As[akq+3][acol] = f2tf(ra.w);
#pragma unroll
    for (int j = 0; j < 4; j++) {
        Bs[j*4+0][tid] = f2tf(rb[j].x); Bs[j*4+1][tid] = f2tf(rb[j].y);
        Bs[j*4+2][tid] = f2tf(rb[j].z); Bs[j*4+3][tid] = f2tf(rb[j].w);
    }
    __syncthreads();

    float acc[2][8][4];
#pragma unroll
    for (int mi = 0; mi < 2; mi++)
#pragma unroll
        for (int nj = 0; nj < 8; nj++)
#pragma unroll
            for (int r = 0; r < 4; r++) acc[mi][nj][r] = 0.f;

    for (int k0 = 0; k0 < KCAT; k0 += 16) {
        const bool more = (k0 + 16) < KCAT;
        if (more) {
            ra = *(const float4*)(A + (long long)ah * KCAT + (k0+16) + akq);
            load_kvrow16(rb, kvc, pec, kvnew, penew, b, bt, spos, k0 + 16);
        }
#pragma unroll
        for (int s = 0; s < 2; s++) {
            const int kk = s * 8;
            const int key0 = 8 * ((kk >> 2) & 3);
            const int key1 = 8 * (((kk >> 2) + 1) & 3);
            unsigned af[2][4];
#pragma unroll
            for (int mi = 0; mi < 2; mi++) {
                int r0 = wh + mi*16 + gid;
                af[mi][0] = As[kk+tig  ][ r0    ^ key0];
                af[mi][1] = As[kk+tig  ][(r0+8) ^ key0];
                af[mi][2] = As[kk+tig+4][ r0    ^ key1];
                af[mi][3] = As[kk+tig+4][(r0+8) ^ key1];
            }
            unsigned bf[8][2];
#pragma unroll
            for (int nj = 0; nj < 8; nj++) {
                bf[nj][0] = Bs[kk+tig  ][wt + nj*8 + gid];
                bf[nj][1] = Bs[kk+tig+4][wt + nj*8 + gid];
            }
#pragma unroll
            for (int mi = 0; mi < 2; mi++)
#pragma unroll
                for (int nj = 0; nj < 8; nj++)
                    mma8(acc[mi][nj], af[mi], bf[nj]);
        }
        __syncthreads();
        if (more) {
            As[akq+0][acol] = f2tf(ra.x); As[akq+1][acol] = f2tf(ra.y);
            As[akq+2][acol] = f2tf(ra.z); As[akq+3][acol] = f2tf(ra.w);
#pragma unroll
            for (int j = 0; j < 4; j++) {
                Bs[j*4+0][tid] = f2tf(rb[j].x); Bs[j*4+1][tid] = f2tf(rb[j].y);
                Bs[j*4+2][tid] = f2tf(rb[j].z); Bs[j*4+3][tid] = f2tf(rb[j].w);
            }
        }
        __syncthreads();
    }

#pragma unroll
    for (int mi = 0; mi < 2; mi++)
#pragma unroll
        for (int nj = 0; nj < 8; nj++) {
            float* cp = C + (long long)(wh + mi*16 + gid) * MAXS + t0 + wt + nj*8 + 2*tig;
            *(float2*)cp              = make_float2(acc[mi][nj][0], acc[mi][nj][1]);
            *(float2*)(cp + 8*MAXS)   = make_float2(acc[mi][nj][2], acc[mi][nj][3]);
        }
}

// ---------------- softmax ----------------
__global__ void __launch_bounds__(256) softmax_kernel(float* __restrict__ S,
                                                      const int* __restrict__ spos_p)
{
    int row = blockIdx.x;
    float* p = S + (long long)row * MAXS;
    int end = *spos_p + 1;
    if (end > MAXS) end = MAXS;
    int tid = threadIdx.x;
    float v[16];
    float mx = -1e30f;
#pragma unroll
    for (int j = 0; j < 16; j++) {
        int t = tid + j * 256;
        float x = (t < end) ? p[t] : -1e30f;
        v[j] = x;
        mx = fmaxf(mx, x);
    }
    mx = blockMax256(mx);
    float sum = 0.f;
#pragma unroll
    for (int j = 0; j < 16; j++) {
        int t = tid + j * 256;
        float e = (t < end) ? __expf(v[j] - mx) : 0.f;
        v[j] = e;
        sum += e;
    }
    sum = blockSum256(sum);
    float inv = 1.f / sum;
#pragma unroll
    for (int j = 0; j < 16; j++) {
        int t = tid + j * 256;
        p[t] = v[j] * inv;
    }
}

// =====================================================================
// olat (TF32 MMA): O[b,h,c] = sum_t P[b,h,t]*kv[b,t,c]
// tile 64h x 128c, warps 2x4 (32h x 32c each), K = t (4096)
// =====================================================================
__global__ void __launch_bounds__(256) olat_mma(
    const float* __restrict__ P, const float* __restrict__ kvc,
    const float* __restrict__ kvnew, float* __restrict__ O,
    const int* __restrict__ spos_p)
{
    const int b = blockIdx.z, spos = *spos_p;
    const int c0 = blockIdx.x * 128, h0 = blockIdx.y * 64;
    const float* A = P + ((long long)b * H + h0) * MAXS;
    float* C = O + ((long long)b * H + h0) * KVLR;

    __shared__ unsigned As[16][72];
    __shared__ unsigned Bs[16][136];

    const int tid = threadIdx.x, lane = tid & 31, wid = tid >> 5;
    const int gid = lane >> 2, tig = lane & 3;
    const int wh = (wid & 1) * 32, wc = (wid >> 1) * 32;

    const int ah = tid >> 2, akq = (tid & 3) * 4;
    const int acol = ah ^ (8 * ((akq >> 2) & 3));

    float4 ra; float4 rb[2];

    ra = *(const float4*)(A + (long long)ah * MAXS + akq);
#pragma unroll
    for (int j = 0; j < 2; j++) {
        int t = wid + 8*j;
        const float* src = (t == spos) ? (kvnew + (long long)b * KVLR + c0 + lane*4)
                                       : (kvc + ((long long)b * MAXS + t) * KVLR + c0 + lane*4);
        rb[j] = *(const float4*)src;
    }
    As[akq+0][acol] = f2tf(ra.x); As[akq+1][acol] = f2tf(ra.y);
    As[akq+2][acol] = f2tf(ra.z); As[akq+3][acol] = f2tf(ra.w);
#pragma unroll
    for (int j = 0; j < 2; j++) {
        uint4 u = make_uint4(f2tf(rb[j].x), f2tf(rb[j].y), f2tf(rb[j].z), f2tf(rb[j].w));
        *(uint4*)&Bs[wid + 8*j][lane*4] = u;
    }
    __syncthreads();

    float acc[2][4][4];
#pragma unroll
    for (int mi = 0; mi < 2; mi++)
#pragma unroll
        for (int nj = 0; nj < 4; nj++)
#pragma unroll
            for (int r = 0; r < 4; r++) acc[mi][nj][r] = 0.f;

    for (int k0 = 0; k0 < MAXS; k0 += 16) {
        const bool more = (k0 + 16) < MAXS;
        if (more) {
            ra = *(const float4*)(A + (long long)ah * MAXS + (k0+16) + akq);
#pragma unroll
            for (int j = 0; j < 2; j++) {
                int t = k0 + 16 + wid + 8*j;
                const float* src = (t == spos) ? (kvnew + (long long)b * KVLR + c0 + lane*4)
                                               : (kvc + ((long long)b * MAXS + t) * KVLR + c0 + lane*4);
                rb[j] = *(const float4*)src;
            }
        }
#pragma unroll
        for (int s = 0; s < 2; s++) {
            const int kk = s * 8;
            const int key0 = 8 * ((kk >> 2) & 3);
            const int key1 = 8 * (((kk >> 2) + 1) & 3);
            unsigned af[2][4];
#pragma unroll
            for (int mi = 0; mi < 2; mi++) {
                int r0 = wh + mi*16 + gid;
                af[mi][0] = As[kk+tig  ][ r0    ^ key0];
                af[mi][1] = As[kk+tig  ][(r0+8) ^ key0];
                af[mi][2] = As[kk+tig+4][ r0    ^ key1];
                af[mi][3] = As[kk+tig+4][(r0+8) ^ key1];
            }
            unsigned bf[4][2];
#pragma unroll
            for (int nj = 0; nj < 4; nj++) {
                bf[nj][0] = Bs[kk+tig  ][wc + nj*8 + gid];
                bf[nj][1] = Bs[kk+tig+4][wc + nj*8 + gid];
            }
#pragma unroll
            for (int mi = 0; mi < 2; mi++)
#pragma unroll
                for (int nj = 0; nj < 4; nj++)
                    mma8(acc[mi][nj], af[mi], bf[nj]);
        }
        __syncthreads();
        if (more) {
            As[akq+0][acol] = f2tf(ra.x); As[akq+1][acol] = f2tf(ra.y);
            As[akq+2][acol] = f2tf(ra.z); As[akq+3][acol] = f2tf(ra.w);
#pragma unroll
            for (int j = 0; j < 2; j++) {
                uint4 u = make_uint4(f2tf(rb[j].x), f2tf(rb[j].y), f2tf(rb[j].z), f2tf(rb[j].w));
                *(uint4*)&Bs[wid + 8*j][lane*4] = u;
            }
        }
        __syncthreads();
    }

#pragma unroll
    for (int mi = 0; mi < 2; mi++)
#pragma unroll
        for (int nj = 0; nj < 4; nj++) {
            float* cp = C + (long long)(wh + mi*16 + gid) * KVLR + c0 + wc + nj*8 + 2*tig;
            *(float2*)cp            = make_float2(acc[mi][nj][0], acc[mi][nj][1]);
            *(float2*)(cp + 8*KVLR) = make_float2(acc[mi][nj][2], acc[mi][nj][3]);
        }
}

// =====================================================================
// FFMA split-K GEMV (kept for small/odd shapes: kvfull, ohead)
// =====================================================================
template<int BN, int TN>
__global__ void __launch_bounds__(256) gemv_splitk(
    const float* __restrict__ A, const float* __restrict__ B, float* __restrict__ C,
    int N, int lda, int ldb, int ldc, int kChunk,
    long long aB, long long bB, long long cB)
{
    A += (long long)blockIdx.z * aB;
    B += (long long)blockIdx.z * bB;
    C += (long long)blockIdx.z * cB;
    const int n0 = blockIdx.x * BN;
    const int ks = blockIdx.y * kChunk;
    const int ke = ks + kChunk;

    __shared__ __align__(16) ull   As2[16][32];
    __shared__ __align__(16) float Bs [16][BN];

    const int tid = threadIdx.x;
    const int tx = tid & 31, ty = tid >> 5;

    const bool aon = tid < 128;
    const int am = tid >> 2, akq = (tid & 3) << 2;
    constexpr int PER = BN / 64;
    const int bn  = tid % BN;
    const int bkq = (tid / BN) * PER;
    const bool bon = (n0 + bn) < N;

    float4 ra = make_float4(0,0,0,0);
    float4 rb[PER];
#pragma unroll
    for (int j = 0; j < PER; j++) rb[j] = make_float4(0,0,0,0);

    if (aon) ra = *(const float4*)(A + (long long)am * lda + ks + akq);
    if (bon) {
        const float* bp = B + (long long)(n0 + bn) * ldb + ks + bkq * 4;
#pragma unroll
        for (int j = 0; j < PER; j++) rb[j] = *(const float4*)(bp + j * 4);
    }
    if (aon) {
        As2[akq+0][am] = dup2(ra.x); As2[akq+1][am] = dup2(ra.y);
        As2[akq+2][am] = dup2(ra.z); As2[akq+3][am] = dup2(ra.w);
    }
#pragma unroll
    for (int j = 0; j < PER; j++) {
        Bs[(bkq+j)*4+0][bn] = rb[j].x;
        Bs[(bkq+j)*4+1][bn] = rb[j].y;
        Bs[(bkq+j)*4+2][bn] = rb[j].z;
        Bs[(bkq+j)*4+3][bn] = rb[j].w;
    }
    __syncthreads();

    ull acc[4][TN/2];
#pragma unroll
    for (int m = 0; m < 4; m++)
#pragma unroll
        for (int j = 0; j < TN/2; j++) acc[m][j] = 0ull;

    for (int k0 = ks; k0 < ke; k0 += 16) {
        const bool more = (k0 + 16) < ke;
        if (more) {
            if (aon) ra = *(const float4*)(A + (long long)am * lda + (k0+16) + akq);
            if (bon) {
                const float* bp = B + (long long)(n0 + bn) * ldb + (k0+16) + bkq * 4;
#pragma unroll
                for (int j = 0; j < PER; j++) rb[j] = *(const float4*)(bp + j * 4);
            }
        }
#pragma unroll
        for (int kk = 0; kk < 16; kk++) {
            ulonglong2 a01 = *(const ulonglong2*)&As2[kk][ty*4];
            ulonglong2 a23 = *(const ulonglong2*)&As2[kk][ty*4+2];
            ull a[4] = {a01.x, a01.y, a23.x, a23.y};
            ull bq[TN/2];
            if constexpr (TN == 8) {
                ulonglong2 b0 = *(const ulonglong2*)&Bs[kk][tx*8];
                ulonglong2 b1 = *(const ulonglong2*)&Bs[kk][tx*8+4];
                bq[0]=b0.x; bq[1]=b0.y; bq[2]=b1.x; bq[3]=b1.y;
            } else {
                ulonglong2 b0 = *(const ulonglong2*)&Bs[kk][tx*4];
                bq[0]=b0.x; bq[1]=b0.y;
            }
#pragma unroll
            for (int m = 0; m < 4; m++)
#pragma unroll
                for (int j = 0; j < TN/2; j++)
                    acc[m][j] = fma2(a[m], bq[j], acc[m][j]);
        }
        __syncthreads();
        if (more) {
            if (aon) {
                As2[akq+0][am] = dup2(ra.x); As2[akq+1][am] = dup2(ra.y);
                As2[akq+2][am] = dup2(ra.z); As2[akq+3][am] = dup2(ra.w);
            }
#pragma unroll
            for (int j = 0; j < PER; j++) {
                Bs[(bkq+j)*4+0][bn] = rb[j].x;
                Bs[(bkq+j)*4+1][bn] = rb[j].y;
                Bs[(bkq+j)*4+2][bn] = rb[j].z;
                Bs[(bkq+j)*4+3][bn] = rb[j].w;
            }
        }
        __syncthreads();
    }

    const int nb = n0 + tx * TN;
#pragma unroll
    for (int m = 0; m < 4; m++) {
        float* cp = C + (long long)(ty*4+m) * ldc + nb;
#pragma unroll
        for (int j = 0; j < TN/2; j++) {
            float2 f = u2f(acc[m][j]);
            if (nb + 2*j     < N) atomicAdd(cp + 2*j,     f.x);
            if (nb + 2*j + 1 < N) atomicAdd(cp + 2*j + 1, f.y);
        }
    }
}

// ---------------- launch ----------------
extern "C" void kernel_launch(void* const* d_in, const int* in_sizes, int n_in,
                              void* d_out, int out_size)
{
    const float* x        = (const float*)d_in[0];
    const float* fc       = (const float*)d_in[1];
    const float* fs       = (const float*)d_in[2];
    const float* kvc      = (const float*)d_in[3];
    const float* pec      = (const float*)d_in[4];
    const float* wq_a     = (const float*)d_in[5];
    const float* q_norm_w = (const float*)d_in[6];
    const float* wq_b     = (const float*)d_in[7];
    const float* wkv_a    = (const float*)d_in[8];
    const float* kv_norm  = (const float*)d_in[9];
    const float* wkv_b    = (const float*)d_in[10];
    const float* wo       = (const float*)d_in[11];
    const int*   spos     = (const int*)d_in[12];
    float*       out      = (float*)d_out;

    float *qlat, *kvfull, *kvnew, *penew, *q, *qcat, *scores, *olat, *ohead;
    cudaGetSymbolAddress((void**)&qlat,   g_qlat);
    cudaGetSymbolAddress((void**)&kvfull, g_kvfull);
    cudaGetSymbolAddress((void**)&kvnew,  g_kvnew);
    cudaGetSymbolAddress((void**)&penew,  g_penew);
    cudaGetSymbolAddress((void**)&q,      g_q);
    cudaGetSymbolAddress((void**)&qcat,   g_qcat);
    cudaGetSymbolAddress((void**)&scores, g_scores);
    cudaGetSymbolAddress((void**)&olat,   g_olat);
    cudaGetSymbolAddress((void**)&ohead,  g_ohead);

    cudaMemsetAsync(qlat,   0, (size_t)BATCH * QLR  * 4);
    cudaMemsetAsync(kvfull, 0, (size_t)BATCH * KCAT * 4);
    cudaMemsetAsync(q,      0, (size_t)BATCH * QDIM * 4);
    cudaMemsetAsync(ohead,  0, (size_t)BATCH * ODIM * 4);
    cudaMemsetAsync(out,    0, (size_t)out_size * 4);

    dim3 blk(256);

    // q_lat = x @ wq_a^T   (N=1536, K=7168): 6 n-tiles x 16 k-splits
    gemv_mma<<<dim3(6,16,1), blk>>>(x, wq_a, qlat, DIM, DIM, QLR, 448);
    // kv_full = x @ wkv_a^T (N=576, K=7168) — FFMA (N not /256)
    gemv_splitk<256,8><<<dim3(3,32,1), blk>>>(x, wkv_a, kvfull, KCAT, DIM, DIM, KCAT, 224, 0,0,0);
    rmsnorm_kernel<<<32, 256>>>(qlat, q_norm_w, QLR);
    kvprep_kernel<<<32, 256>>>(kvfull, kv_norm, fc, fs, kvnew, penew);
    // q = q_lat @ wq_b^T   (N=24576, K=1536): 96 x 3
    gemv_mma<<<dim3(96,3,1), blk>>>(qlat, wq_b, q, QLR, QLR, QDIM, 512);
    qrope_kernel<<<512, 256>>>(q, fc, fs, qcat);
    qabs_kernel<<<128, 512>>>(q, wkv_b, qcat);
    // scores (TF32 MMA)
    scores_mma<<<dim3(MAXS/256, H/64, BATCH), blk>>>(qcat, kvc, pec, kvnew, penew, scores, spos);
    softmax_kernel<<<BATCH * H, 256>>>(scores, spos);
    // olat (TF32 MMA)
    olat_mma<<<dim3(KVLR/128, H/64, BATCH), blk>>>(scores, kvc, kvnew, olat, spos);
    // ohead per head (FFMA, small)
    gemv_splitk<128,4><<<dim3(1,1,H), blk>>>(olat, wkv_b + 128*KVLR, ohead,
                                             DV, H*KVLR, KVLR, ODIM, KVLR,
                                             (long long)KVLR, (long long)256*KVLR, (long long)DV);
    // out = ohead @ wo^T   (N=7168, K=16384): 28 x 8
    gemv_mma<<<dim3(28,8,1), blk>>>(ohead, wo, out, ODIM, ODIM, DIM, 2048);
}